// round 7
// baseline (speedup 1.0000x reference)
#include <cuda_runtime.h>
#include <cuda_fp16.h>

#define N_NODES 100000
#define N_PAD   100032
#define K 32
#define D 64
#define CAP 96                   // per-dst bucket capacity (Poisson(32) tail ~1e-18)
#define NEG_SLOPE 0.2f

// Persistent scratch — replay-safe by invariant:
//   g_cnt starts zero (.bss) and is re-zeroed by k_gather every launch.
//   Everything else is fully rewritten every launch.
__device__ __align__(128) __half g_h16[(size_t)N_PAD * D];
__device__ float g_si[N_PAD];
__device__ float g_sj[N_PAD];
__device__ int   g_cnt[N_PAD];
__device__ __align__(128) int   g_bkt[(size_t)N_NODES * CAP];

// ---------------------------------------------------------------------------
// Kernel 1 (fused): [a] pure edge transpose (src-only scatter into per-dst
// buckets — needs ONLY the edges array, so it overlaps with the GEMM), and
// [b] h = embed @ W via mma.sync.m16n8k16 (fp16 in, fp32 accum) with
// si = h.a_i, sj = h.a_j computed in fp32 from c-fragments.
// 8 warps/block, 16 rows/warp -> 128 rows/block; block also scatters its own
// 128 src rows' 4096 edges. grid 782.
// ---------------------------------------------------------------------------
__global__ void __launch_bounds__(256) k_gemm_scatter(const float* __restrict__ embed,
                                                      const float* __restrict__ W,
                                                      const float* __restrict__ att,
                                                      const int* __restrict__ edges) {
    __shared__ unsigned sw2[32][72];   // 72-word stride: b-frag LDS conflict-free
    __shared__ float s_att[128];

    int t = threadIdx.x;
    int base = blockIdx.x * 128;

    // --- stage W (fp16x2 pairs) + att ---
    for (int idx = t; idx < 32 * 64; idx += 256) {
        int kk = idx >> 6, n = idx & 63;
        __half2 h2 = __floats2half2_rn(__ldg(&W[(2 * kk) * 64 + n]),
                                       __ldg(&W[(2 * kk + 1) * 64 + n]));
        sw2[kk][n] = *reinterpret_cast<unsigned*>(&h2);
    }
    if (t < 128) s_att[t] = __ldg(&att[t]);

    // --- [a] edge transpose for this block's 128 src rows (latency work,
    //     no smem, overlaps with staging and the MMA pipeline below) ---
#pragma unroll
    for (int i = 0; i < 16; i++) {
        int j = t + i * 256;                 // 0..4095, coalesced
        int src = base + (j >> 5);
        if (src < N_NODES) {
            int dst = __ldg(&edges[(size_t)base * K + j]);
            if (dst != src) {                // self K-edges are invalid
                int pos = atomicAdd(&g_cnt[dst], 1);
                if (pos < CAP)
                    g_bkt[(size_t)dst * CAP + pos] = src;
            }
        }
    }
    __syncthreads();

    // --- [b] tensor-core GEMM ---
    int lane = t & 31, w = t >> 5;
    int r0 = base + w * 16 + (lane >> 2);
    int r1 = r0 + 8;
    int kq = (lane & 3) * 2;

    unsigned a[4][4];
#pragma unroll
    for (int ks = 0; ks < 4; ks++) {
        int k = ks * 16 + kq;
        float2 f0 = (r0 < N_NODES) ? *reinterpret_cast<const float2*>(embed + (size_t)r0 * D + k)     : make_float2(0.f, 0.f);
        float2 f1 = (r1 < N_NODES) ? *reinterpret_cast<const float2*>(embed + (size_t)r1 * D + k)     : make_float2(0.f, 0.f);
        float2 f2 = (r0 < N_NODES) ? *reinterpret_cast<const float2*>(embed + (size_t)r0 * D + k + 8) : make_float2(0.f, 0.f);
        float2 f3 = (r1 < N_NODES) ? *reinterpret_cast<const float2*>(embed + (size_t)r1 * D + k + 8) : make_float2(0.f, 0.f);
        __half2 h;
        h = __floats2half2_rn(f0.x, f0.y); a[ks][0] = *reinterpret_cast<unsigned*>(&h);
        h = __floats2half2_rn(f1.x, f1.y); a[ks][1] = *reinterpret_cast<unsigned*>(&h);
        h = __floats2half2_rn(f2.x, f2.y); a[ks][2] = *reinterpret_cast<unsigned*>(&h);
        h = __floats2half2_rn(f3.x, f3.y); a[ks][3] = *reinterpret_cast<unsigned*>(&h);
    }

    int nb = lane >> 2;
    float psi0 = 0.f, psj0 = 0.f, psi1 = 0.f, psj1 = 0.f;

#pragma unroll
    for (int nt = 0; nt < 8; nt++) {
        float c0 = 0.f, c1 = 0.f, c2 = 0.f, c3 = 0.f;
#pragma unroll
        for (int ks = 0; ks < 4; ks++) {
            unsigned b0 = sw2[ks * 8 + (lane & 3)][nt * 8 + nb];
            unsigned b1 = sw2[ks * 8 + (lane & 3) + 4][nt * 8 + nb];
            asm volatile(
                "mma.sync.aligned.m16n8k16.row.col.f32.f16.f16.f32 "
                "{%0,%1,%2,%3}, {%4,%5,%6,%7}, {%8,%9}, {%0,%1,%2,%3};"
                : "+f"(c0), "+f"(c1), "+f"(c2), "+f"(c3)
                : "r"(a[ks][0]), "r"(a[ks][1]), "r"(a[ks][2]), "r"(a[ks][3]),
                  "r"(b0), "r"(b1));
        }
        int col = nt * 8 + kq;

        float ai0 = s_att[col],      ai1 = s_att[col + 1];
        float aj0 = s_att[64 + col], aj1 = s_att[64 + col + 1];
        psi0 += c0 * ai0 + c1 * ai1;
        psj0 += c0 * aj0 + c1 * aj1;
        psi1 += c2 * ai0 + c3 * ai1;
        psj1 += c2 * aj0 + c3 * aj1;

        __half2 h01 = __floats2half2_rn(c0, c1);
        __half2 h23 = __floats2half2_rn(c2, c3);
        if (r0 < N_NODES) *reinterpret_cast<__half2*>(g_h16 + (size_t)r0 * D + col) = h01;
        if (r1 < N_NODES) *reinterpret_cast<__half2*>(g_h16 + (size_t)r1 * D + col) = h23;
    }

#pragma unroll
    for (int o = 1; o <= 2; o <<= 1) {
        psi0 += __shfl_xor_sync(0xffffffffu, psi0, o);
        psj0 += __shfl_xor_sync(0xffffffffu, psj0, o);
        psi1 += __shfl_xor_sync(0xffffffffu, psi1, o);
        psj1 += __shfl_xor_sync(0xffffffffu, psj1, o);
    }
    if ((lane & 3) == 0) {
        if (r0 < N_NODES) { g_si[r0] = psi0; g_sj[r0] = psj0; }
        if (r1 < N_NODES) { g_si[r1] = psi1; g_sj[r1] = psj1; }
    }
}

// ---------------------------------------------------------------------------
// Kernel 2: gather + finalize. Warp per dst; lane owns cols [4c..4c+3],
// c = lane&15, two edges per iteration (one per half-warp). Bucket (src only)
// staged in smem; e recomputed per edge: exp(lrelu(si[dst] + sj[src])).
// Self-loop = appended entry src=dst (same formula). Pad entry masked by
// idx<=deg predicate. Re-zeroes g_cnt[dst] for the next launch (replay inv.).
// out = normalize((sum h[src]*e) / denom + bias)
// ---------------------------------------------------------------------------
__global__ void __launch_bounds__(256) k_gather(const float* __restrict__ bias,
                                                float* __restrict__ out) {
    __shared__ int sb[8][CAP + 2];

    int lane = threadIdx.x & 31;
    int w    = threadIdx.x >> 5;
    int c    = lane & 15;
    int half = lane >> 4;
    int dst  = blockIdx.x * 8 + w;

    int deg = min(g_cnt[dst], CAP);
    const int* bp = g_bkt + (size_t)dst * CAP;

    for (int j = lane; j < deg; j += 32)
        sb[w][j] = bp[j];

    if (lane == 0) {
        sb[w][deg]     = dst;   // self loop: same e formula as normal edges
        sb[w][deg + 1] = dst;   // pad (contribution masked to zero)
        g_cnt[dst] = 0;         // reset for next launch
    }
    __syncwarp();

    float si = __ldg(&g_si[dst]);   // broadcast, 1 sector

    float4 acc = make_float4(0.f, 0.f, 0.f, 0.f);
    float  den = 0.f;

    int iters = (deg + 2) >> 1;     // covers deg bucket entries + self + pad
#pragma unroll 4
    for (int j = 0; j < iters; j++) {
        int idx = 2 * j + half;
        int s = sb[w][idx];                       // LDS.32, 2 bcast addrs
        float a = si + __ldg(&g_sj[s]);           // 1 sector per half-warp
        a = (a >= 0.f) ? a : NEG_SLOPE * a;
        float e = __expf(a);
        e = (idx <= deg) ? e : 0.f;               // mask pad
        uint2 u = reinterpret_cast<const uint2*>(g_h16 + (size_t)s * D)[c];
        float2 fa = __half22float2(*reinterpret_cast<__half2*>(&u.x));
        float2 fb = __half22float2(*reinterpret_cast<__half2*>(&u.y));
        acc.x += fa.x * e; acc.y += fa.y * e;
        acc.z += fb.x * e; acc.w += fb.y * e;
        den += e;
    }

    // Merge half-warp partials (cols duplicated across halves).
    acc.x += __shfl_xor_sync(0xffffffffu, acc.x, 16);
    acc.y += __shfl_xor_sync(0xffffffffu, acc.y, 16);
    acc.z += __shfl_xor_sync(0xffffffffu, acc.z, 16);
    acc.w += __shfl_xor_sync(0xffffffffu, acc.w, 16);
    den   += __shfl_xor_sync(0xffffffffu, den,   16);

    float4 bv = __ldg(reinterpret_cast<const float4*>(bias) + c);
    float inv = 1.f / (den + 1e-16f);
    float vx = acc.x * inv + bv.x;
    float vy = acc.y * inv + bv.y;
    float vz = acc.z * inv + bv.z;
    float vw = acc.w * inv + bv.w;

    float ss = vx * vx + vy * vy + vz * vz + vw * vw;
#pragma unroll
    for (int o = 8; o > 0; o >>= 1)
        ss += __shfl_xor_sync(0xffffffffu, ss, o);

    float scale = 1.f / fmaxf(sqrtf(ss), 1e-12f);
    if (half == 0) {
        reinterpret_cast<float4*>(out + (size_t)dst * D)[c] =
            make_float4(vx * scale, vy * scale, vz * scale, vw * scale);
    }
}

// ---------------------------------------------------------------------------
extern "C" void kernel_launch(void* const* d_in, const int* in_sizes, int n_in,
                              void* d_out, int out_size) {
    const float* embed = (const float*)d_in[0];
    const float* W     = (const float*)d_in[1];
    const float* att   = (const float*)d_in[2];
    const float* bias  = (const float*)d_in[3];
    const int*   edges = (const int*)d_in[7];
    float* out = (float*)d_out;

    k_gemm_scatter<<<(N_NODES + 127) / 128, 256>>>(embed, W, att, edges);  // 782
    k_gather      <<<N_NODES / 8, 256>>>(bias, out);                       // 12500
}

// round 8
// speedup vs baseline: 1.2492x; 1.2492x over previous
#include <cuda_runtime.h>
#include <cuda_fp16.h>

#define N_NODES 100000
#define N_PAD   100032
#define K 32
#define D 64
#define CAP 96                   // per-dst bucket capacity (Poisson(32) tail ~1e-18)
#define NEG_SLOPE 0.2f

// Persistent scratch — replay-safe by invariant:
//   g_cnt starts zero (.bss) and is re-zeroed by k_gather every launch.
//   Everything else is fully rewritten every launch.
__device__ __align__(128) __half g_h16[(size_t)N_PAD * D];
__device__ float g_si[N_PAD];
__device__ float g_sj[N_PAD];
__device__ int   g_cnt[N_PAD];
__device__ __align__(128) int2  g_bkt[(size_t)N_NODES * CAP];

// ---------------------------------------------------------------------------
// Kernel 1 (tensor-core): h = embed @ W via mma.sync.m16n8k16 (fp16 in,
// fp32 accum); si = h.a_i, sj = h.a_j in fp32 from c-fragments + quad shfl.
// 8 warps/block, 16 rows/warp -> 128 rows/block, grid 782. (Round-6 version.)
// ---------------------------------------------------------------------------
__global__ void __launch_bounds__(256) k_gemm(const float* __restrict__ embed,
                                              const float* __restrict__ W,
                                              const float* __restrict__ att) {
    __shared__ unsigned sw2[32][72];   // 72-word stride: b-frag LDS conflict-free
    __shared__ float s_att[128];

    int t = threadIdx.x;
    int base = blockIdx.x * 128;

    for (int idx = t; idx < 32 * 64; idx += 256) {
        int kk = idx >> 6, n = idx & 63;
        __half2 h2 = __floats2half2_rn(__ldg(&W[(2 * kk) * 64 + n]),
                                       __ldg(&W[(2 * kk + 1) * 64 + n]));
        sw2[kk][n] = *reinterpret_cast<unsigned*>(&h2);
    }
    if (t < 128) s_att[t] = __ldg(&att[t]);
    __syncthreads();

    int lane = t & 31, w = t >> 5;
    int r0 = base + w * 16 + (lane >> 2);
    int r1 = r0 + 8;
    int kq = (lane & 3) * 2;

    unsigned a[4][4];
#pragma unroll
    for (int ks = 0; ks < 4; ks++) {
        int k = ks * 16 + kq;
        float2 f0 = (r0 < N_NODES) ? *reinterpret_cast<const float2*>(embed + (size_t)r0 * D + k)     : make_float2(0.f, 0.f);
        float2 f1 = (r1 < N_NODES) ? *reinterpret_cast<const float2*>(embed + (size_t)r1 * D + k)     : make_float2(0.f, 0.f);
        float2 f2 = (r0 < N_NODES) ? *reinterpret_cast<const float2*>(embed + (size_t)r0 * D + k + 8) : make_float2(0.f, 0.f);
        float2 f3 = (r1 < N_NODES) ? *reinterpret_cast<const float2*>(embed + (size_t)r1 * D + k + 8) : make_float2(0.f, 0.f);
        __half2 h;
        h = __floats2half2_rn(f0.x, f0.y); a[ks][0] = *reinterpret_cast<unsigned*>(&h);
        h = __floats2half2_rn(f1.x, f1.y); a[ks][1] = *reinterpret_cast<unsigned*>(&h);
        h = __floats2half2_rn(f2.x, f2.y); a[ks][2] = *reinterpret_cast<unsigned*>(&h);
        h = __floats2half2_rn(f3.x, f3.y); a[ks][3] = *reinterpret_cast<unsigned*>(&h);
    }

    int nb = lane >> 2;
    float psi0 = 0.f, psj0 = 0.f, psi1 = 0.f, psj1 = 0.f;

#pragma unroll
    for (int nt = 0; nt < 8; nt++) {
        float c0 = 0.f, c1 = 0.f, c2 = 0.f, c3 = 0.f;
#pragma unroll
        for (int ks = 0; ks < 4; ks++) {
            unsigned b0 = sw2[ks * 8 + (lane & 3)][nt * 8 + nb];
            unsigned b1 = sw2[ks * 8 + (lane & 3) + 4][nt * 8 + nb];
            asm volatile(
                "mma.sync.aligned.m16n8k16.row.col.f32.f16.f16.f32 "
                "{%0,%1,%2,%3}, {%4,%5,%6,%7}, {%8,%9}, {%0,%1,%2,%3};"
                : "+f"(c0), "+f"(c1), "+f"(c2), "+f"(c3)
                : "r"(a[ks][0]), "r"(a[ks][1]), "r"(a[ks][2]), "r"(a[ks][3]),
                  "r"(b0), "r"(b1));
        }
        int col = nt * 8 + kq;

        float ai0 = s_att[col],      ai1 = s_att[col + 1];
        float aj0 = s_att[64 + col], aj1 = s_att[64 + col + 1];
        psi0 += c0 * ai0 + c1 * ai1;
        psj0 += c0 * aj0 + c1 * aj1;
        psi1 += c2 * ai0 + c3 * ai1;
        psj1 += c2 * aj0 + c3 * aj1;

        __half2 h01 = __floats2half2_rn(c0, c1);
        __half2 h23 = __floats2half2_rn(c2, c3);
        if (r0 < N_NODES) *reinterpret_cast<__half2*>(g_h16 + (size_t)r0 * D + col) = h01;
        if (r1 < N_NODES) *reinterpret_cast<__half2*>(g_h16 + (size_t)r1 * D + col) = h23;
    }

#pragma unroll
    for (int o = 1; o <= 2; o <<= 1) {
        psi0 += __shfl_xor_sync(0xffffffffu, psi0, o);
        psj0 += __shfl_xor_sync(0xffffffffu, psj0, o);
        psi1 += __shfl_xor_sync(0xffffffffu, psi1, o);
        psj1 += __shfl_xor_sync(0xffffffffu, psj1, o);
    }
    if ((lane & 3) == 0) {
        if (r0 < N_NODES) { g_si[r0] = psi0; g_sj[r0] = psj0; }
        if (r1 < N_NODES) { g_si[r1] = psi1; g_sj[r1] = psj1; }
    }
}

// ---------------------------------------------------------------------------
// Kernel 2: fill per-dst buckets with (src, e). 4 independent edges/thread
// (MLP=4 hides the si-load -> atomic-return -> scattered-store chains).
// Softmax without max-shift (shift-invariant; alpha is O(1) here).
// Relies on g_cnt == 0 at entry (zeroed by k_gather at end of prior launch).
// ---------------------------------------------------------------------------
__global__ void __launch_bounds__(256) k_fill(const int* __restrict__ edges) {
    int t = threadIdx.x;
    int base = blockIdx.x * 1024;             // 1024 edges per block

    int   dst[4], src[4];
    float e[4];
#pragma unroll
    for (int i = 0; i < 4; i++) {
        int j = base + i * 256 + t;           // coalesced edge index
        src[i] = j >> 5;
        dst[i] = __ldg(&edges[j]);
    }
#pragma unroll
    for (int i = 0; i < 4; i++) {
        float a = __ldg(&g_si[dst[i]]) + g_sj[src[i]];
        a = fmaxf(a, NEG_SLOPE * a);          // leaky relu (NEG_SLOPE in (0,1))
        e[i] = __expf(a);
    }
#pragma unroll
    for (int i = 0; i < 4; i++) {
        if (dst[i] != src[i]) {               // self K-edges are invalid
            int pos = atomicAdd(&g_cnt[dst[i]], 1);
            if (pos < CAP)
                g_bkt[(size_t)dst[i] * CAP + pos] = make_int2(src[i], __float_as_int(e[i]));
        }
    }
}

// ---------------------------------------------------------------------------
// Kernel 3: gather + finalize. Warp per dst; lane owns cols [4c..4c+3],
// c = lane&15, two edges per iteration (one per half-warp). Bucket (src,e)
// + self-loop + zero pad staged in smem -> branch-free
// LDS.64 bcast -> LDG.64 -> 4 FMA loop (e precomputed: minimal instructions).
// Re-zeroes g_cnt[dst] for the next launch.
// out = normalize((sum h[src]*e) / denom + bias)
// ---------------------------------------------------------------------------
__global__ void __launch_bounds__(256) k_gather(const float* __restrict__ bias,
                                                float* __restrict__ out) {
    __shared__ int2 sb[8][CAP + 2];

    int lane = threadIdx.x & 31;
    int w    = threadIdx.x >> 5;
    int c    = lane & 15;
    int half = lane >> 4;
    int dst  = blockIdx.x * 8 + w;

    int deg = min(g_cnt[dst], CAP);
    const int2* bp = g_bkt + (size_t)dst * CAP;

    for (int j = lane; j < deg; j += 32)
        sb[w][j] = bp[j];

    // Self loop appended; zero pad after it. Reset cnt for next launch.
    float a = g_si[dst] + g_sj[dst];
    a = fmaxf(a, NEG_SLOPE * a);
    float es = __expf(a);
    if (lane == 0) {
        sb[w][deg]     = make_int2(dst, __float_as_int(es));
        sb[w][deg + 1] = make_int2(dst, 0);
        g_cnt[dst] = 0;
    }
    __syncwarp();

    float4 acc = make_float4(0.f, 0.f, 0.f, 0.f);
    float  den = 0.f;

    int iters = (deg + 2) >> 1;          // deg entries + self + pad
#pragma unroll 4
    for (int j = 0; j < iters; j++) {
        int2 ent = sb[w][2 * j + half];  // LDS.64, 2 bcast addrs (adjacent banks)
        float e = __int_as_float(ent.y);
        uint2 u = reinterpret_cast<const uint2*>(g_h16 + (size_t)ent.x * D)[c];
        float2 fa = __half22float2(*reinterpret_cast<__half2*>(&u.x));
        float2 fb = __half22float2(*reinterpret_cast<__half2*>(&u.y));
        acc.x += fa.x * e; acc.y += fa.y * e;
        acc.z += fb.x * e; acc.w += fb.y * e;
        den += e;
    }

    // Merge half-warp partials (cols duplicated across halves).
    acc.x += __shfl_xor_sync(0xffffffffu, acc.x, 16);
    acc.y += __shfl_xor_sync(0xffffffffu, acc.y, 16);
    acc.z += __shfl_xor_sync(0xffffffffu, acc.z, 16);
    acc.w += __shfl_xor_sync(0xffffffffu, acc.w, 16);
    den   += __shfl_xor_sync(0xffffffffu, den,   16);

    float4 bv = __ldg(reinterpret_cast<const float4*>(bias) + c);
    float inv = 1.f / (den + 1e-16f);
    float vx = acc.x * inv + bv.x;
    float vy = acc.y * inv + bv.y;
    float vz = acc.z * inv + bv.z;
    float vw = acc.w * inv + bv.w;

    float ss = vx * vx + vy * vy + vz * vz + vw * vw;
#pragma unroll
    for (int o = 8; o > 0; o >>= 1)
        ss += __shfl_xor_sync(0xffffffffu, ss, o);

    float scale = 1.f / fmaxf(sqrtf(ss), 1e-12f);
    if (half == 0) {
        reinterpret_cast<float4*>(out + (size_t)dst * D)[c] =
            make_float4(vx * scale, vy * scale, vz * scale, vw * scale);
    }
}

// ---------------------------------------------------------------------------
extern "C" void kernel_launch(void* const* d_in, const int* in_sizes, int n_in,
                              void* d_out, int out_size) {
    const float* embed = (const float*)d_in[0];
    const float* W     = (const float*)d_in[1];
    const float* att   = (const float*)d_in[2];
    const float* bias  = (const float*)d_in[3];
    const int*   edges = (const int*)d_in[7];
    float* out = (float*)d_out;

    k_gemm  <<<(N_NODES + 127) / 128, 256>>>(embed, W, att);  // 782 blocks
    k_fill  <<<(N_NODES * K) / 1024, 256>>>(edges);           // 3125 blocks
    k_gather<<<N_NODES / 8, 256>>>(bias, out);                // 12500 blocks
}